// round 11
// baseline (speedup 1.0000x reference)
#include <cuda_runtime.h>
#include <cuda_bf16.h>
#include <cstdint>

// Shapes (fixed): N_NODES=8192, K_FRE=2048, K_HIGH=6144, D=512
#define NN 8192
#define KF 2048
#define KH 6144
#define DD 512

// ---------------- scratch (device globals) ----------------------------------
static __device__ __nv_bfloat16 g_WT_hi [DD * DD];
static __device__ __nv_bfloat16 g_WT_lo [DD * DD];
static __device__ __nv_bfloat16 g_preT_hi[DD * NN];
static __device__ __nv_bfloat16 g_preT_lo[DD * NN];
static __device__ __nv_bfloat16 g_t1T_hi [DD * KF];
static __device__ __nv_bfloat16 g_t1T_lo [DD * KF];
static __device__ __nv_bfloat16 g_t3T_hi [DD * KH];
static __device__ __nv_bfloat16 g_t3T_lo [DD * KH];
static __device__ float         g_low   [NN * DD];
static __device__ float         g_alpha [2];

// ---------------- PTX helpers (baseline ISA only) -----------------------------
__device__ __forceinline__ uint32_t smem_u32(const void* p) {
    uint32_t a;
    asm("{ .reg .u64 t; cvta.to.shared.u64 t, %1; cvt.u32.u64 %0, t; }"
        : "=r"(a) : "l"(p));
    return a;
}
__device__ __forceinline__ void ldsm_x4(uint32_t r[4], uint32_t addr) {
    asm volatile("ldmatrix.sync.aligned.m8n8.x4.shared.b16 {%0,%1,%2,%3}, [%4];"
        : "=r"(r[0]), "=r"(r[1]), "=r"(r[2]), "=r"(r[3]) : "r"(addr));
}
__device__ __forceinline__ void mma16816(float c[4], const uint32_t a[4],
                                         uint32_t b0, uint32_t b1) {
    asm volatile("mma.sync.aligned.m16n8k16.row.col.f32.bf16.bf16.f32 "
        "{%0,%1,%2,%3}, {%4,%5,%6,%7}, {%8,%9}, {%0,%1,%2,%3};"
        : "+f"(c[0]), "+f"(c[1]), "+f"(c[2]), "+f"(c[3])
        : "r"(a[0]), "r"(a[1]), "r"(a[2]), "r"(a[3]), "r"(b0), "r"(b1));
}
__device__ __forceinline__ void cp16(uint32_t saddr, const void* g) {
    asm volatile("cp.async.cg.shared.global [%0], [%1], 16;" :: "r"(saddr), "l"(g));
}
#define CP_COMMIT()  asm volatile("cp.async.commit_group;" ::: "memory")
#define CP_WAIT1()   asm volatile("cp.async.wait_group 1;" ::: "memory")
#define CP_WAIT0()   asm volatile("cp.async.wait_group 0;" ::: "memory")

// ---------------- small kernels ------------------------------------------------
__global__ void softmax2_kernel(const float* __restrict__ alpha) {
    float a0 = alpha[0], a1 = alpha[1];
    float m = fmaxf(a0, a1);
    float e0 = expf(a0 - m), e1 = expf(a1 - m);
    float inv = 1.0f / (e0 + e1);
    g_alpha[0] = e0 * inv;
    g_alpha[1] = e1 * inv;
}

__global__ void wt_split_kernel(const float* __restrict__ W) {
    __shared__ float t[32][33];
    int bx = blockIdx.x * 32, by = blockIdx.y * 32;
    int tx = threadIdx.x, ty = threadIdx.y;
    t[ty][tx] = W[(size_t)(by + ty) * DD + bx + tx];
    __syncthreads();
    float v = t[tx][ty];
    int n = bx + ty, k = by + tx;
    __nv_bfloat16 h = __float2bfloat16(v);
    float lv = v - __bfloat162float(h);
    g_WT_hi[(size_t)n * DD + k] = h;
    g_WT_lo[(size_t)n * DD + k] = __float2bfloat16(lv);
}

// ---------------- split-bf16 mma.sync GEMM --------------------------------------
// C[M,512] = A[M,K](fp32) @ Bt[512,K]^T (bf16 hi/lo).
// CTA 128x128, 256 threads (8 warps), warp tile 16x128 (A conversion 1x),
// kc=32, 3-stage ring with ONE syncthreads per iter, TWO CTAs per SM
// (96 KB smem each) so barrier/conversion bubbles of one CTA are covered
// by the other CTA's MMA stream. ks order staggered by warp parity.
// B smem row = [hi(32) | lo(32)] in one 128B swizzled atom.
// MODE 0: write C^T split bf16 into (CThi1,CTlo1), ld1
// MODE 3: rows < M1 -> (CThi1,CTlo1,ld1); rows >= M1 -> (CThi2,CTlo2,ld2), row-M1
// MODE 1: Cf = alpha[aidx]*C
// MODE 2: Cf = relu(max(alpha[aidx]*C, other) + bias)
#define CTA_M 128
#define CTA_N 128
#define OFF_A 0            // 128 rows x 128B (32 fp32) = 16 KB
#define OFF_B 16384        // 128 rows x 128B (hi|lo)   = 16 KB
#define STAGE 32768
#define NSTAGE 3
#define SMEM_TOTAL (NSTAGE * STAGE)   // 96 KB -> 2 CTAs/SM

template<int MODE>
__global__ __launch_bounds__(256, 2)
void gemm_mma(const float* __restrict__ A1, const float* __restrict__ A2, int M1,
              const __nv_bfloat16* __restrict__ Bhi,
              const __nv_bfloat16* __restrict__ Blo,
              int K,
              float* __restrict__ Cf,
              __nv_bfloat16* __restrict__ CThi1, __nv_bfloat16* __restrict__ CTlo1, int ld1,
              __nv_bfloat16* __restrict__ CThi2, __nv_bfloat16* __restrict__ CTlo2, int ld2,
              int aidx, const float* __restrict__ other,
              const float* __restrict__ bias)
{
    extern __shared__ char smem[];
    const uint32_t sb = smem_u32(smem);
    const int tid = threadIdx.x;
    const int wid = tid >> 5, lid = tid & 31;
    const int brow = blockIdx.y * CTA_M, bcol = blockIdx.x * CTA_N;
    const int wm = wid * 16;                 // 8 warps, one 16-row band each
    const int grp = lid >> 2, ctid = lid & 3;
    const int kss = wid & 1;                 // ks-order stagger

    const float* Abase;
    if (MODE == 3 && brow >= M1) Abase = A2 + (size_t)(brow - M1) * K;
    else                         Abase = A1 + (size_t)brow * K;

    // B ldmatrix lane geometry (128B rows, XOR swizzle)
    const int lb_row = (lid & 7) + ((lid >> 4) << 3);
    const int lb_col = ((lid >> 3) & 1) << 4;

    float acc[16][4];
    #pragma unroll
    for (int j = 0; j < 16; j++)
        #pragma unroll
        for (int q = 0; q < 4; q++) acc[j][q] = 0.0f;

    const int nt = K >> 5;

    // A fp32: 128 rows x 8 chunks(16B) = 1024; 4/thread.
    // B: 128 rows x 8 chunks (4 hi | 4 lo) = 1024; 4/thread.
    #define CPA(sidx, kt) do { \
        uint32_t abse = sb + (uint32_t)(sidx) * STAGE; \
        _Pragma("unroll") \
        for (int r = 0; r < 4; r++) { \
            int idx = tid + (r << 8); \
            int row = idx >> 3, c = idx & 7; \
            uint32_t dst = abse + OFF_A + row * 128 + (uint32_t)((c ^ (row & 7)) << 4); \
            cp16(dst, Abase + (size_t)row * K + (kt) + (c << 2)); \
        } \
        _Pragma("unroll") \
        for (int r = 0; r < 4; r++) { \
            int idx = tid + (r << 8); \
            int row = idx >> 3, c = idx & 7; \
            uint32_t dst = abse + OFF_B + row * 128 + (uint32_t)((c ^ (row & 7)) << 4); \
            const __nv_bfloat16* src = (c < 4) \
                ? (Bhi + (size_t)(bcol + row) * K + (kt) + (c << 3)) \
                : (Blo + (size_t)(bcol + row) * K + (kt) + ((c - 4) << 3)); \
            cp16(dst, src); \
        } } while (0)

    // ---- prologue: fill stages 0,1 (iters 0,1) ----
    CPA(0, 0);  CP_COMMIT();
    CPA(1, 32); CP_COMMIT();

    for (int it = 0; it < nt; it++) {
        const int cs = it % NSTAGE;
        const uint32_t cbase = sb + (uint32_t)cs * STAGE;
        if (it + 1 < nt) { CP_WAIT1(); } else { CP_WAIT0(); }
        __syncthreads();                       // single barrier per iter
        // refill slot (it+2)%3 == (it-1)%3 (drained before this barrier)
        if (it + 2 < nt) {
            CPA((it + 2) % NSTAGE, (it + 2) << 5);
            CP_COMMIT();
        }

        #pragma unroll
        for (int s = 0; s < 2; s++) {
            const int ks = kss ^ s;            // staggered k16 order per warp
            // ---- A fragment (m16k16): LDS.64 fp32 pair -> split bf16 hi/lo ----
            uint32_t ah[4], al[4];
            {
                const int r0 = wm + grp;
                #pragma unroll
                for (int u = 0; u < 4; u++) {
                    const int rr = r0 + (u & 1) * 8;
                    const int cb = (ks * 16 + ctid * 2 + (u >> 1) * 8) * 4;   // col byte
                    uint32_t addr = cbase + OFF_A + rr * 128 +
                        (uint32_t)((((cb >> 4) ^ (rr & 7)) << 4) | (cb & 15));
                    float f0, f1;
                    asm volatile("ld.shared.v2.f32 {%0,%1}, [%2];"
                                 : "=f"(f0), "=f"(f1) : "r"(addr));
                    uint32_t h;
                    asm("cvt.rn.bf16x2.f32 %0, %1, %2;" : "=r"(h) : "f"(f1), "f"(f0));
                    float h0 = __uint_as_float(h << 16);
                    float h1 = __uint_as_float(h & 0xFFFF0000u);
                    float l0 = f0 - h0, l1 = f1 - h1;
                    uint32_t l;
                    asm("cvt.rn.bf16x2.f32 %0, %1, %2;" : "=r"(l) : "f"(l1), "f"(l0));
                    ah[u] = h; al[u] = l;
                }
            }
            // ---- B: n128 consumed in 4 chunks of n32 ----
            #pragma unroll
            for (int c = 0; c < 4; c++) {
                uint32_t bh[2][4], bl[2][4];
                #pragma unroll
                for (int p = 0; p < 2; p++) {
                    const int prow = lb_row + (c * 2 + p) * 16;
                    const int sw = (prow & 7) << 4;
                    uint32_t base = cbase + OFF_B + prow * 128;
                    ldsm_x4(bh[p], base + (uint32_t)((ks * 32 + lb_col) ^ sw));
                    ldsm_x4(bl[p], base + (uint32_t)((64 + ks * 32 + lb_col) ^ sw));
                }
                #pragma unroll
                for (int p = 0; p < 2; p++)
                    #pragma unroll
                    for (int h = 0; h < 2; h++) {
                        float* cc = acc[c * 4 + p * 2 + h];
                        mma16816(cc, ah, bh[p][h * 2], bh[p][h * 2 + 1]);
                        mma16816(cc, al, bh[p][h * 2], bh[p][h * 2 + 1]);
                        mma16816(cc, ah, bl[p][h * 2], bl[p][h * 2 + 1]);
                    }
            }
        }
    }

    // ---- epilogue ----
    if (MODE == 0 || MODE == 3) {
        #pragma unroll
        for (int j = 0; j < 16; j++) {
            const int c0 = bcol + j * 8 + ctid * 2;
            #pragma unroll
            for (int q = 0; q < 4; q++) {
                const int mm = brow + wm + grp + (q >> 1) * 8;
                const int cc = c0 + (q & 1);
                float v = acc[j][q];
                __nv_bfloat16 h = __float2bfloat16(v);
                __nv_bfloat16 l = __float2bfloat16(v - __bfloat162float(h));
                if (MODE == 0 || mm < M1) {
                    CThi1[(size_t)cc * ld1 + mm] = h;
                    CTlo1[(size_t)cc * ld1 + mm] = l;
                } else {
                    CThi2[(size_t)cc * ld2 + (mm - M1)] = h;
                    CTlo2[(size_t)cc * ld2 + (mm - M1)] = l;
                }
            }
        }
    } else {
        const float as = g_alpha[aidx];
        const int m0 = brow + wm + grp;
        #pragma unroll
        for (int j = 0; j < 16; j++) {
            const int c0 = bcol + j * 8 + ctid * 2;
            if (MODE == 1) {
                float2 v0 = make_float2(as * acc[j][0], as * acc[j][1]);
                float2 v1 = make_float2(as * acc[j][2], as * acc[j][3]);
                *reinterpret_cast<float2*>(Cf + (size_t)m0 * DD + c0) = v0;
                *reinterpret_cast<float2*>(Cf + (size_t)(m0 + 8) * DD + c0) = v1;
            } else {
                float2 o0 = *reinterpret_cast<const float2*>(other + (size_t)m0 * DD + c0);
                float2 o1 = *reinterpret_cast<const float2*>(other + (size_t)(m0 + 8) * DD + c0);
                float2 bb = *reinterpret_cast<const float2*>(bias + c0);
                float2 v0, v1;
                v0.x = fmaxf(fmaxf(as * acc[j][0], o0.x) + bb.x, 0.0f);
                v0.y = fmaxf(fmaxf(as * acc[j][1], o0.y) + bb.y, 0.0f);
                v1.x = fmaxf(fmaxf(as * acc[j][2], o1.x) + bb.x, 0.0f);
                v1.y = fmaxf(fmaxf(as * acc[j][3], o1.y) + bb.y, 0.0f);
                *reinterpret_cast<float2*>(Cf + (size_t)m0 * DD + c0) = v0;
                *reinterpret_cast<float2*>(Cf + (size_t)(m0 + 8) * DD + c0) = v1;
            }
        }
    }
    #undef CPA
}

// ---------------- host launch ----------------------------------------------------
extern "C" void kernel_launch(void* const* d_in, const int* in_sizes, int n_in,
                              void* d_out, int out_size)
{
    const float* x     = (const float*)d_in[0];
    const float* W     = (const float*)d_in[1];
    const float* alpha = (const float*)d_in[2];
    const float* bias  = (const float*)d_in[3];
    const float* s0    = (const float*)d_in[4];
    const float* s1    = (const float*)d_in[5];
    const float* s2    = (const float*)d_in[6];
    const float* s3    = (const float*)d_in[7];
    float* out = (float*)d_out;

    __nv_bfloat16 *WTh, *WTl, *pTh, *pTl, *t1h, *t1l, *t3h, *t3l;
    float* low;
    cudaGetSymbolAddress((void**)&WTh, g_WT_hi);
    cudaGetSymbolAddress((void**)&WTl, g_WT_lo);
    cudaGetSymbolAddress((void**)&pTh, g_preT_hi);
    cudaGetSymbolAddress((void**)&pTl, g_preT_lo);
    cudaGetSymbolAddress((void**)&t1h, g_t1T_hi);
    cudaGetSymbolAddress((void**)&t1l, g_t1T_lo);
    cudaGetSymbolAddress((void**)&t3h, g_t3T_hi);
    cudaGetSymbolAddress((void**)&t3l, g_t3T_lo);
    cudaGetSymbolAddress((void**)&low, g_low);

    static bool attr_done = false;
    if (!attr_done) {
        cudaFuncSetAttribute(gemm_mma<0>, cudaFuncAttributeMaxDynamicSharedMemorySize, SMEM_TOTAL);
        cudaFuncSetAttribute(gemm_mma<1>, cudaFuncAttributeMaxDynamicSharedMemorySize, SMEM_TOTAL);
        cudaFuncSetAttribute(gemm_mma<2>, cudaFuncAttributeMaxDynamicSharedMemorySize, SMEM_TOTAL);
        cudaFuncSetAttribute(gemm_mma<3>, cudaFuncAttributeMaxDynamicSharedMemorySize, SMEM_TOTAL);
        attr_done = true;
    }

    softmax2_kernel<<<1, 1>>>(alpha);
    wt_split_kernel<<<dim3(16, 16), dim3(32, 32)>>>(W);

    const dim3 grid(DD / CTA_N, NN / CTA_M);   // (4, 64) = 256 CTAs, 2/SM

    // pre^T = (x @ W)^T (split bf16)
    gemm_mma<0><<<grid, 256, SMEM_TOTAL>>>(
        x, nullptr, NN, WTh, WTl, DD,
        nullptr, pTh, pTl, NN, nullptr, nullptr, 0, 0, nullptr, nullptr);
    // merged: t1^T (rows<2048 from s1) + t3^T (rows>=2048 from s3)
    gemm_mma<3><<<grid, 256, SMEM_TOTAL>>>(
        s1, s3, KF, pTh, pTl, NN,
        nullptr, t1h, t1l, KF, t3h, t3l, KH, 0, nullptr, nullptr);
    // low = a0 * (s0 @ t1)
    gemm_mma<1><<<grid, 256, SMEM_TOTAL>>>(
        s0, nullptr, NN, t1h, t1l, KF,
        low, nullptr, nullptr, 0, nullptr, nullptr, 0, 0, nullptr, nullptr);
    // out = relu(max(a1*(s2 @ t3), low) + bias)
    gemm_mma<2><<<grid, 256, SMEM_TOTAL>>>(
        s2, nullptr, NN, t3h, t3l, KH,
        out, nullptr, nullptr, 0, nullptr, nullptr, 1, 1, low, bias);
}

// round 12
// speedup vs baseline: 1.0913x; 1.0913x over previous
#include <cuda_runtime.h>
#include <cuda_bf16.h>
#include <cstdint>

// Shapes (fixed): N_NODES=8192, K_FRE=2048, K_HIGH=6144, D=512
#define NN 8192
#define KF 2048
#define KH 6144
#define DD 512

// ---------------- scratch (device globals) ----------------------------------
static __device__ __nv_bfloat16 g_WT_hi [DD * DD];
static __device__ __nv_bfloat16 g_WT_lo [DD * DD];
static __device__ __nv_bfloat16 g_preT_hi[DD * NN];
static __device__ __nv_bfloat16 g_preT_lo[DD * NN];
static __device__ __nv_bfloat16 g_t1T_hi [DD * KF];
static __device__ __nv_bfloat16 g_t1T_lo [DD * KF];
static __device__ __nv_bfloat16 g_t3T_hi [DD * KH];
static __device__ __nv_bfloat16 g_t3T_lo [DD * KH];
static __device__ float         g_low   [NN * DD];
static __device__ float         g_alpha [2];

// ---------------- PTX helpers (baseline ISA only) -----------------------------
__device__ __forceinline__ uint32_t smem_u32(const void* p) {
    uint32_t a;
    asm("{ .reg .u64 t; cvta.to.shared.u64 t, %1; cvt.u32.u64 %0, t; }"
        : "=r"(a) : "l"(p));
    return a;
}
__device__ __forceinline__ void ldsm_x4(uint32_t r[4], uint32_t addr) {
    asm volatile("ldmatrix.sync.aligned.m8n8.x4.shared.b16 {%0,%1,%2,%3}, [%4];"
        : "=r"(r[0]), "=r"(r[1]), "=r"(r[2]), "=r"(r[3]) : "r"(addr));
}
__device__ __forceinline__ void mma16816(float c[4], const uint32_t a[4],
                                         uint32_t b0, uint32_t b1) {
    asm volatile("mma.sync.aligned.m16n8k16.row.col.f32.bf16.bf16.f32 "
        "{%0,%1,%2,%3}, {%4,%5,%6,%7}, {%8,%9}, {%0,%1,%2,%3};"
        : "+f"(c[0]), "+f"(c[1]), "+f"(c[2]), "+f"(c[3])
        : "r"(a[0]), "r"(a[1]), "r"(a[2]), "r"(a[3]), "r"(b0), "r"(b1));
}
__device__ __forceinline__ void cp16(uint32_t saddr, const void* g) {
    asm volatile("cp.async.cg.shared.global [%0], [%1], 16;" :: "r"(saddr), "l"(g));
}
#define CP_COMMIT()  asm volatile("cp.async.commit_group;" ::: "memory")
#define CP_WAIT1()   asm volatile("cp.async.wait_group 1;" ::: "memory")
#define CP_WAIT0()   asm volatile("cp.async.wait_group 0;" ::: "memory")

// ---------------- small kernels ------------------------------------------------
__global__ void softmax2_kernel(const float* __restrict__ alpha) {
    float a0 = alpha[0], a1 = alpha[1];
    float m = fmaxf(a0, a1);
    float e0 = expf(a0 - m), e1 = expf(a1 - m);
    float inv = 1.0f / (e0 + e1);
    g_alpha[0] = e0 * inv;
    g_alpha[1] = e1 * inv;
}

__global__ void wt_split_kernel(const float* __restrict__ W) {
    __shared__ float t[32][33];
    int bx = blockIdx.x * 32, by = blockIdx.y * 32;
    int tx = threadIdx.x, ty = threadIdx.y;
    t[ty][tx] = W[(size_t)(by + ty) * DD + bx + tx];
    __syncthreads();
    float v = t[tx][ty];
    int n = bx + ty, k = by + tx;
    __nv_bfloat16 h = __float2bfloat16(v);
    float lv = v - __bfloat162float(h);
    g_WT_hi[(size_t)n * DD + k] = h;
    g_WT_lo[(size_t)n * DD + k] = __float2bfloat16(lv);
}

// ---------------- split-bf16 mma.sync GEMM --------------------------------------
// C[M,512] = A[M,K](fp32) @ Bt[512,K]^T (bf16 hi/lo).
// CTA 256x128, 512 threads (16 warps), warp tile 16x128 (A conversion 1x).
// kc=64, 2-stage (R9 base). NEW: A-fragment conversion software-pipelined one
// ks ahead (double-buffered frags) so the LDS->cvt chain hides under the
// 48-MMA burst of the previous k16 step.
// MODE 0: write C^T split bf16 into (CThi1,CTlo1), ld1
// MODE 3: rows < M1 -> (CThi1,CTlo1,ld1); rows >= M1 -> (CThi2,CTlo2,ld2), row-M1
// MODE 1: Cf = alpha[aidx]*C
// MODE 2: Cf = relu(max(alpha[aidx]*C, other) + bias)
#define CTA_M 256
#define CTA_N 128
#define OFF_A32 0          // 256 x 64 fp32 = 64 KB
#define OFF_BH  65536      // 128 x 64 bf16 = 16 KB
#define OFF_BL  81920      // 16 KB
#define STAGE   98304
#define SMEM_TOTAL (2 * STAGE)   // 192 KB

template<int MODE>
__global__ __launch_bounds__(512, 1)
void gemm_mma(const float* __restrict__ A1, const float* __restrict__ A2, int M1,
              const __nv_bfloat16* __restrict__ Bhi,
              const __nv_bfloat16* __restrict__ Blo,
              int K,
              float* __restrict__ Cf,
              __nv_bfloat16* __restrict__ CThi1, __nv_bfloat16* __restrict__ CTlo1, int ld1,
              __nv_bfloat16* __restrict__ CThi2, __nv_bfloat16* __restrict__ CTlo2, int ld2,
              int aidx, const float* __restrict__ other,
              const float* __restrict__ bias)
{
    extern __shared__ char smem[];
    const uint32_t sb = smem_u32(smem);
    const int tid = threadIdx.x;
    const int wid = tid >> 5, lid = tid & 31;
    const int brow = blockIdx.y * CTA_M, bcol = blockIdx.x * CTA_N;
    const int wm = wid * 16;                 // 16 warps, one 16-row band each
    const int grp = lid >> 2, ctid = lid & 3;

    const float* Abase;
    if (MODE == 3 && brow >= M1) Abase = A2 + (size_t)(brow - M1) * K;
    else                         Abase = A1 + (size_t)brow * K;

    // B ldmatrix lane geometry (128B rows, XOR swizzle)
    const int lb_row = (lid & 7) + ((lid >> 4) << 3);
    const int lb_col = ((lid >> 3) & 1) << 4;

    float acc[16][4];
    #pragma unroll
    for (int j = 0; j < 16; j++)
        #pragma unroll
        for (int q = 0; q < 4; q++) acc[j][q] = 0.0f;

    const int nt = K >> 6;

    // A fp32: 256 rows x 64 f32 = 4096 16B-chunks; 8/thread.
    // B: 128 rows x 64 bf16 (hi+lo) = 1024 chunks each; 2/thread each.
    #define CPA(sidx, kt) do { \
        uint32_t abse = sb + (uint32_t)(sidx) * STAGE; \
        _Pragma("unroll") \
        for (int r = 0; r < 8; r++) { \
            int idx = tid + (r << 9); \
            int row = idx >> 4, c = idx & 15; \
            uint32_t dst = abse + OFF_A32 + row * 256 + (uint32_t)((c ^ ((row & 7) << 1)) << 4); \
            cp16(dst, Abase + (size_t)row * K + (kt) + (c << 2)); \
        } \
        _Pragma("unroll") \
        for (int r = 0; r < 2; r++) { \
            int idx = tid + (r << 9); \
            int row = idx >> 3, c = idx & 7; \
            uint32_t off = (uint32_t)(row * 128 + ((c << 4) ^ ((row & 7) << 4))); \
            size_t g = (size_t)(bcol + row) * K + (kt) + (c << 3); \
            cp16(abse + OFF_BH + off, Bhi + g); \
            cp16(abse + OFF_BL + off, Blo + g); \
        } } while (0)

    // A-fragment conversion for one k16 step (m16k16) into (AH, AL)
    #define CONVA(cbase_, ks_, AH, AL) do { \
        const int r0_ = wm + grp; \
        _Pragma("unroll") \
        for (int u = 0; u < 4; u++) { \
            const int rr = r0_ + (u & 1) * 8; \
            const int kk = (ks_) * 16 + ctid * 2 + (u >> 1) * 8; \
            uint32_t addr = (cbase_) + OFF_A32 + rr * 256 + \
                (uint32_t)(((((kk >> 2) ^ ((rr & 7) << 1))) << 4) | ((kk & 3) << 2)); \
            float f0, f1; \
            asm volatile("ld.shared.v2.f32 {%0,%1}, [%2];" \
                         : "=f"(f0), "=f"(f1) : "r"(addr)); \
            uint32_t h_; \
            asm("cvt.rn.bf16x2.f32 %0, %1, %2;" : "=r"(h_) : "f"(f1), "f"(f0)); \
            float h0_ = __uint_as_float(h_ << 16); \
            float h1_ = __uint_as_float(h_ & 0xFFFF0000u); \
            float l0_ = f0 - h0_, l1_ = f1 - h1_; \
            uint32_t l_; \
            asm("cvt.rn.bf16x2.f32 %0, %1, %2;" : "=r"(l_) : "f"(l1_), "f"(l0_)); \
            (AH)[u] = h_; (AL)[u] = l_; \
        } } while (0)

    // ---- prologue: fill both stages ----
    CPA(0, 0);  CP_COMMIT();
    CPA(1, 64); CP_COMMIT();

    for (int it = 0; it < nt; it++) {
        const int cs = it & 1;
        const uint32_t cbase = sb + (uint32_t)cs * STAGE;
        if (it + 1 < nt) { CP_WAIT1(); } else { CP_WAIT0(); }
        __syncthreads();

        // double-buffered A fragments, converted one ks ahead
        uint32_t ah[2][4], al[2][4];
        CONVA(cbase, 0, ah[0], al[0]);

        #pragma unroll
        for (int ks = 0; ks < 4; ks++) {
            const int cur = ks & 1, nxt = cur ^ 1;
            if (ks < 3) CONVA(cbase, ks + 1, ah[nxt], al[nxt]);   // hides under MMA burst

            // ---- B: n128 consumed in 4 chunks of n32 ----
            #pragma unroll
            for (int c = 0; c < 4; c++) {
                uint32_t bh[2][4], bl[2][4];
                #pragma unroll
                for (int p = 0; p < 2; p++) {
                    const int prow = lb_row + (c * 2 + p) * 16;
                    uint32_t boff = (uint32_t)(prow * 128 +
                                     ((lb_col + ks * 32) ^ ((prow & 7) << 4)));
                    ldsm_x4(bh[p], cbase + OFF_BH + boff);
                    ldsm_x4(bl[p], cbase + OFF_BL + boff);
                }
                #pragma unroll
                for (int p = 0; p < 2; p++)
                    #pragma unroll
                    for (int h = 0; h < 2; h++) {
                        float* cc = acc[c * 4 + p * 2 + h];
                        mma16816(cc, ah[cur], bh[p][h * 2], bh[p][h * 2 + 1]);
                        mma16816(cc, al[cur], bh[p][h * 2], bh[p][h * 2 + 1]);
                        mma16816(cc, ah[cur], bl[p][h * 2], bl[p][h * 2 + 1]);
                    }
            }
        }

        __syncthreads();
        if (it + 2 < nt) {
            CPA(cs, (it + 2) << 6);
            CP_COMMIT();
        }
    }

    // ---- epilogue ----
    if (MODE == 0 || MODE == 3) {
        #pragma unroll
        for (int j = 0; j < 16; j++) {
            const int c0 = bcol + j * 8 + ctid * 2;
            #pragma unroll
            for (int q = 0; q < 4; q++) {
                const int mm = brow + wm + grp + (q >> 1) * 8;
                const int cc = c0 + (q & 1);
                float v = acc[j][q];
                __nv_bfloat16 h = __float2bfloat16(v);
                __nv_bfloat16 l = __float2bfloat16(v - __bfloat162float(h));
                if (MODE == 0 || mm < M1) {
                    CThi1[(size_t)cc * ld1 + mm] = h;
                    CTlo1[(size_t)cc * ld1 + mm] = l;
                } else {
                    CThi2[(size_t)cc * ld2 + (mm - M1)] = h;
                    CTlo2[(size_t)cc * ld2 + (mm - M1)] = l;
                }
            }
        }
    } else {
        const float as = g_alpha[aidx];
        const int m0 = brow + wm + grp;
        #pragma unroll
        for (int j = 0; j < 16; j++) {
            const int c0 = bcol + j * 8 + ctid * 2;
            if (MODE == 1) {
                float2 v0 = make_float2(as * acc[j][0], as * acc[j][1]);
                float2 v1 = make_float2(as * acc[j][2], as * acc[j][3]);
                *reinterpret_cast<float2*>(Cf + (size_t)m0 * DD + c0) = v0;
                *reinterpret_cast<float2*>(Cf + (size_t)(m0 + 8) * DD + c0) = v1;
            } else {
                float2 o0 = *reinterpret_cast<const float2*>(other + (size_t)m0 * DD + c0);
                float2 o1 = *reinterpret_cast<const float2*>(other + (size_t)(m0 + 8) * DD + c0);
                float2 bb = *reinterpret_cast<const float2*>(bias + c0);
                float2 v0, v1;
                v0.x = fmaxf(fmaxf(as * acc[j][0], o0.x) + bb.x, 0.0f);
                v0.y = fmaxf(fmaxf(as * acc[j][1], o0.y) + bb.y, 0.0f);
                v1.x = fmaxf(fmaxf(as * acc[j][2], o1.x) + bb.x, 0.0f);
                v1.y = fmaxf(fmaxf(as * acc[j][3], o1.y) + bb.y, 0.0f);
                *reinterpret_cast<float2*>(Cf + (size_t)m0 * DD + c0) = v0;
                *reinterpret_cast<float2*>(Cf + (size_t)(m0 + 8) * DD + c0) = v1;
            }
        }
    }
    #undef CPA
    #undef CONVA
}

// ---------------- host launch ----------------------------------------------------
extern "C" void kernel_launch(void* const* d_in, const int* in_sizes, int n_in,
                              void* d_out, int out_size)
{
    const float* x     = (const float*)d_in[0];
    const float* W     = (const float*)d_in[1];
    const float* alpha = (const float*)d_in[2];
    const float* bias  = (const float*)d_in[3];
    const float* s0    = (const float*)d_in[4];
    const float* s1    = (const float*)d_in[5];
    const float* s2    = (const float*)d_in[6];
    const float* s3    = (const float*)d_in[7];
    float* out = (float*)d_out;

    __nv_bfloat16 *WTh, *WTl, *pTh, *pTl, *t1h, *t1l, *t3h, *t3l;
    float* low;
    cudaGetSymbolAddress((void**)&WTh, g_WT_hi);
    cudaGetSymbolAddress((void**)&WTl, g_WT_lo);
    cudaGetSymbolAddress((void**)&pTh, g_preT_hi);
    cudaGetSymbolAddress((void**)&pTl, g_preT_lo);
    cudaGetSymbolAddress((void**)&t1h, g_t1T_hi);
    cudaGetSymbolAddress((void**)&t1l, g_t1T_lo);
    cudaGetSymbolAddress((void**)&t3h, g_t3T_hi);
    cudaGetSymbolAddress((void**)&t3l, g_t3T_lo);
    cudaGetSymbolAddress((void**)&low, g_low);

    static bool attr_done = false;
    if (!attr_done) {
        cudaFuncSetAttribute(gemm_mma<0>, cudaFuncAttributeMaxDynamicSharedMemorySize, SMEM_TOTAL);
        cudaFuncSetAttribute(gemm_mma<1>, cudaFuncAttributeMaxDynamicSharedMemorySize, SMEM_TOTAL);
        cudaFuncSetAttribute(gemm_mma<2>, cudaFuncAttributeMaxDynamicSharedMemorySize, SMEM_TOTAL);
        cudaFuncSetAttribute(gemm_mma<3>, cudaFuncAttributeMaxDynamicSharedMemorySize, SMEM_TOTAL);
        attr_done = true;
    }

    softmax2_kernel<<<1, 1>>>(alpha);
    wt_split_kernel<<<dim3(16, 16), dim3(32, 32)>>>(W);

    const dim3 grid(DD / CTA_N, NN / CTA_M);   // (4, 32) = 128 CTAs

    // pre^T = (x @ W)^T (split bf16)
    gemm_mma<0><<<grid, 512, SMEM_TOTAL>>>(
        x, nullptr, NN, WTh, WTl, DD,
        nullptr, pTh, pTl, NN, nullptr, nullptr, 0, 0, nullptr, nullptr);
    // merged: t1^T (rows<2048 from s1) + t3^T (rows>=2048 from s3)
    gemm_mma<3><<<grid, 512, SMEM_TOTAL>>>(
        s1, s3, KF, pTh, pTl, NN,
        nullptr, t1h, t1l, KF, t3h, t3l, KH, 0, nullptr, nullptr);
    // low = a0 * (s0 @ t1)
    gemm_mma<1><<<grid, 512, SMEM_TOTAL>>>(
        s0, nullptr, NN, t1h, t1l, KF,
        low, nullptr, nullptr, 0, nullptr, nullptr, 0, 0, nullptr, nullptr);
    // out = relu(max(a1*(s2 @ t3), low) + bias)
    gemm_mma<2><<<grid, 512, SMEM_TOTAL>>>(
        s2, nullptr, NN, t3h, t3l, KH,
        out, nullptr, nullptr, 0, nullptr, nullptr, 1, 1, low, bias);
}

// round 13
// speedup vs baseline: 1.1019x; 1.0098x over previous
#include <cuda_runtime.h>
#include <cuda_bf16.h>
#include <cstdint>

// Shapes (fixed): N_NODES=8192, K_FRE=2048, K_HIGH=6144, D=512
#define NN 8192
#define KF 2048
#define KH 6144
#define DD 512

// ---------------- scratch (device globals) ----------------------------------
static __device__ __nv_bfloat16 g_WT_hi [DD * DD];
static __device__ __nv_bfloat16 g_WT_lo [DD * DD];
static __device__ __nv_bfloat16 g_preT_hi[DD * NN];
static __device__ __nv_bfloat16 g_preT_lo[DD * NN];
static __device__ __nv_bfloat16 g_t1T_hi [DD * KF];
static __device__ __nv_bfloat16 g_t1T_lo [DD * KF];
static __device__ __nv_bfloat16 g_t3T_hi [DD * KH];
static __device__ __nv_bfloat16 g_t3T_lo [DD * KH];
static __device__ float         g_low   [NN * DD];
static __device__ float         g_alpha [2];

// ---------------- PTX helpers (baseline ISA only) -----------------------------
__device__ __forceinline__ uint32_t smem_u32(const void* p) {
    uint32_t a;
    asm("{ .reg .u64 t; cvta.to.shared.u64 t, %1; cvt.u32.u64 %0, t; }"
        : "=r"(a) : "l"(p));
    return a;
}
__device__ __forceinline__ void ldsm_x4(uint32_t r[4], uint32_t addr) {
    asm volatile("ldmatrix.sync.aligned.m8n8.x4.shared.b16 {%0,%1,%2,%3}, [%4];"
        : "=r"(r[0]), "=r"(r[1]), "=r"(r[2]), "=r"(r[3]) : "r"(addr));
}
__device__ __forceinline__ void mma16816(float c[4], const uint32_t a[4],
                                         uint32_t b0, uint32_t b1) {
    asm volatile("mma.sync.aligned.m16n8k16.row.col.f32.bf16.bf16.f32 "
        "{%0,%1,%2,%3}, {%4,%5,%6,%7}, {%8,%9}, {%0,%1,%2,%3};"
        : "+f"(c[0]), "+f"(c[1]), "+f"(c[2]), "+f"(c[3])
        : "r"(a[0]), "r"(a[1]), "r"(a[2]), "r"(a[3]), "r"(b0), "r"(b1));
}
__device__ __forceinline__ void cp16(uint32_t saddr, const void* g) {
    asm volatile("cp.async.cg.shared.global [%0], [%1], 16;" :: "r"(saddr), "l"(g));
}
#define CP_COMMIT()  asm volatile("cp.async.commit_group;" ::: "memory")
#define CP_WAIT1()   asm volatile("cp.async.wait_group 1;" ::: "memory")
#define CP_WAIT0()   asm volatile("cp.async.wait_group 0;" ::: "memory")

// ---------------- small kernels ------------------------------------------------
__global__ void softmax2_kernel(const float* __restrict__ alpha) {
    float a0 = alpha[0], a1 = alpha[1];
    float m = fmaxf(a0, a1);
    float e0 = expf(a0 - m), e1 = expf(a1 - m);
    float inv = 1.0f / (e0 + e1);
    g_alpha[0] = e0 * inv;
    g_alpha[1] = e1 * inv;
}

__global__ void wt_split_kernel(const float* __restrict__ W) {
    __shared__ float t[32][33];
    int bx = blockIdx.x * 32, by = blockIdx.y * 32;
    int tx = threadIdx.x, ty = threadIdx.y;
    t[ty][tx] = W[(size_t)(by + ty) * DD + bx + tx];
    __syncthreads();
    float v = t[tx][ty];
    int n = bx + ty, k = by + tx;
    __nv_bfloat16 h = __float2bfloat16(v);
    float lv = v - __bfloat162float(h);
    g_WT_hi[(size_t)n * DD + k] = h;
    g_WT_lo[(size_t)n * DD + k] = __float2bfloat16(lv);
}

// ---------------- split-bf16 mma.sync GEMM --------------------------------------
// C[M,512] = A[M,K](fp32) @ Bt[512,K]^T (bf16 hi/lo).
// CTA 256x128, 512 threads (16 warps), warp tile 16x128 (A conversion 1x).
// kc=64, 2-stage (R9 base). NEW vs R9: MMA nest issued TERM-MAJOR so the
// accumulator-reuse distance is 4 MMAs instead of 1 (covers HMMA RAW latency).
// MODE 0: write C^T split bf16 into (CThi1,CTlo1), ld1
// MODE 3: rows < M1 -> (CThi1,CTlo1,ld1); rows >= M1 -> (CThi2,CTlo2,ld2), row-M1
// MODE 1: Cf = alpha[aidx]*C
// MODE 2: Cf = relu(max(alpha[aidx]*C, other) + bias)
#define CTA_M 256
#define CTA_N 128
#define OFF_A32 0          // 256 x 64 fp32 = 64 KB
#define OFF_BH  65536      // 128 x 64 bf16 = 16 KB
#define OFF_BL  81920      // 16 KB
#define STAGE   98304
#define SMEM_TOTAL (2 * STAGE)   // 192 KB

template<int MODE>
__global__ __launch_bounds__(512, 1)
void gemm_mma(const float* __restrict__ A1, const float* __restrict__ A2, int M1,
              const __nv_bfloat16* __restrict__ Bhi,
              const __nv_bfloat16* __restrict__ Blo,
              int K,
              float* __restrict__ Cf,
              __nv_bfloat16* __restrict__ CThi1, __nv_bfloat16* __restrict__ CTlo1, int ld1,
              __nv_bfloat16* __restrict__ CThi2, __nv_bfloat16* __restrict__ CTlo2, int ld2,
              int aidx, const float* __restrict__ other,
              const float* __restrict__ bias)
{
    extern __shared__ char smem[];
    const uint32_t sb = smem_u32(smem);
    const int tid = threadIdx.x;
    const int wid = tid >> 5, lid = tid & 31;
    const int brow = blockIdx.y * CTA_M, bcol = blockIdx.x * CTA_N;
    const int wm = wid * 16;                 // 16 warps, one 16-row band each
    const int grp = lid >> 2, ctid = lid & 3;

    const float* Abase;
    if (MODE == 3 && brow >= M1) Abase = A2 + (size_t)(brow - M1) * K;
    else                         Abase = A1 + (size_t)brow * K;

    // B ldmatrix lane geometry (128B rows, XOR swizzle)
    const int lb_row = (lid & 7) + ((lid >> 4) << 3);
    const int lb_col = ((lid >> 3) & 1) << 4;

    float acc[16][4];
    #pragma unroll
    for (int j = 0; j < 16; j++)
        #pragma unroll
        for (int q = 0; q < 4; q++) acc[j][q] = 0.0f;

    const int nt = K >> 6;

    // A fp32: 256 rows x 64 f32 = 4096 16B-chunks; 8/thread.
    // B: 128 rows x 64 bf16 (hi+lo) = 1024 chunks each; 2/thread each.
    #define CPA(sidx, kt) do { \
        uint32_t abse = sb + (uint32_t)(sidx) * STAGE; \
        _Pragma("unroll") \
        for (int r = 0; r < 8; r++) { \
            int idx = tid + (r << 9); \
            int row = idx >> 4, c = idx & 15; \
            uint32_t dst = abse + OFF_A32 + row * 256 + (uint32_t)((c ^ ((row & 7) << 1)) << 4); \
            cp16(dst, Abase + (size_t)row * K + (kt) + (c << 2)); \
        } \
        _Pragma("unroll") \
        for (int r = 0; r < 2; r++) { \
            int idx = tid + (r << 9); \
            int row = idx >> 3, c = idx & 7; \
            uint32_t off = (uint32_t)(row * 128 + ((c << 4) ^ ((row & 7) << 4))); \
            size_t g = (size_t)(bcol + row) * K + (kt) + (c << 3); \
            cp16(abse + OFF_BH + off, Bhi + g); \
            cp16(abse + OFF_BL + off, Blo + g); \
        } } while (0)

    // ---- prologue: fill both stages ----
    CPA(0, 0);  CP_COMMIT();
    CPA(1, 64); CP_COMMIT();

    for (int it = 0; it < nt; it++) {
        const int cs = it & 1;
        const uint32_t cbase = sb + (uint32_t)cs * STAGE;
        if (it + 1 < nt) { CP_WAIT1(); } else { CP_WAIT0(); }
        __syncthreads();

        #pragma unroll
        for (int ks = 0; ks < 4; ks++) {
            // ---- A fragment (m16k16): LDS.64 fp32 pair -> split bf16 hi/lo ----
            uint32_t ah[4], al[4];
            {
                const int r0 = wm + grp;
                #pragma unroll
                for (int u = 0; u < 4; u++) {
                    const int rr = r0 + (u & 1) * 8;
                    const int kk = ks * 16 + ctid * 2 + (u >> 1) * 8;
                    uint32_t addr = cbase + OFF_A32 + rr * 256 +
                        (uint32_t)(((((kk >> 2) ^ ((rr & 7) << 1))) << 4) | ((kk & 3) << 2));
                    float f0, f1;
                    asm volatile("ld.shared.v2.f32 {%0,%1}, [%2];"
                                 : "=f"(f0), "=f"(f1) : "r"(addr));
                    uint32_t h;
                    asm("cvt.rn.bf16x2.f32 %0, %1, %2;" : "=r"(h) : "f"(f1), "f"(f0));
                    float h0 = __uint_as_float(h << 16);
                    float h1 = __uint_as_float(h & 0xFFFF0000u);
                    float l0 = f0 - h0, l1 = f1 - h1;
                    uint32_t l;
                    asm("cvt.rn.bf16x2.f32 %0, %1, %2;" : "=r"(l) : "f"(l1), "f"(l0));
                    ah[u] = h; al[u] = l;
                }
            }
            // ---- B: n128 consumed in 4 chunks of n32; MMAs term-major ----
            #pragma unroll
            for (int c = 0; c < 4; c++) {
                uint32_t bh[2][4], bl[2][4];
                #pragma unroll
                for (int p = 0; p < 2; p++) {
                    const int prow = lb_row + (c * 2 + p) * 16;
                    uint32_t boff = (uint32_t)(prow * 128 +
                                     ((lb_col + ks * 32) ^ ((prow & 7) << 4)));
                    ldsm_x4(bh[p], cbase + OFF_BH + boff);
                    ldsm_x4(bl[p], cbase + OFF_BL + boff);
                }
                // term 0: hi x hi   (4 independent accumulators)
                #pragma unroll
                for (int p = 0; p < 2; p++)
                    #pragma unroll
                    for (int h = 0; h < 2; h++)
                        mma16816(acc[c * 4 + p * 2 + h], ah,
                                 bh[p][h * 2], bh[p][h * 2 + 1]);
                // term 1: lo x hi
                #pragma unroll
                for (int p = 0; p < 2; p++)
                    #pragma unroll
                    for (int h = 0; h < 2; h++)
                        mma16816(acc[c * 4 + p * 2 + h], al,
                                 bh[p][h * 2], bh[p][h * 2 + 1]);
                // term 2: hi x lo
                #pragma unroll
                for (int p = 0; p < 2; p++)
                    #pragma unroll
                    for (int h = 0; h < 2; h++)
                        mma16816(acc[c * 4 + p * 2 + h], ah,
                                 bl[p][h * 2], bl[p][h * 2 + 1]);
            }
        }

        __syncthreads();
        if (it + 2 < nt) {
            CPA(cs, (it + 2) << 6);
            CP_COMMIT();
        }
    }

    // ---- epilogue ----
    if (MODE == 0 || MODE == 3) {
        #pragma unroll
        for (int j = 0; j < 16; j++) {
            const int c0 = bcol + j * 8 + ctid * 2;
            #pragma unroll
            for (int q = 0; q < 4; q++) {
                const int mm = brow + wm + grp + (q >> 1) * 8;
                const int cc = c0 + (q & 1);
                float v = acc[j][q];
                __nv_bfloat16 h = __float2bfloat16(v);
                __nv_bfloat16 l = __float2bfloat16(v - __bfloat162float(h));
                if (MODE == 0 || mm < M1) {
                    CThi1[(size_t)cc * ld1 + mm] = h;
                    CTlo1[(size_t)cc * ld1 + mm] = l;
                } else {
                    CThi2[(size_t)cc * ld2 + (mm - M1)] = h;
                    CTlo2[(size_t)cc * ld2 + (mm - M1)] = l;
                }
            }
        }
    } else {
        const float as = g_alpha[aidx];
        const int m0 = brow + wm + grp;
        #pragma unroll
        for (int j = 0; j < 16; j++) {
            const int c0 = bcol + j * 8 + ctid * 2;
            if (MODE == 1) {
                float2 v0 = make_float2(as * acc[j][0], as * acc[j][1]);
                float2 v1 = make_float2(as * acc[j][2], as * acc[j][3]);
                *reinterpret_cast<float2*>(Cf + (size_t)m0 * DD + c0) = v0;
                *reinterpret_cast<float2*>(Cf + (size_t)(m0 + 8) * DD + c0) = v1;
            } else {
                float2 o0 = *reinterpret_cast<const float2*>(other + (size_t)m0 * DD + c0);
                float2 o1 = *reinterpret_cast<const float2*>(other + (size_t)(m0 + 8) * DD + c0);
                float2 bb = *reinterpret_cast<const float2*>(bias + c0);
                float2 v0, v1;
                v0.x = fmaxf(fmaxf(as * acc[j][0], o0.x) + bb.x, 0.0f);
                v0.y = fmaxf(fmaxf(as * acc[j][1], o0.y) + bb.y, 0.0f);
                v1.x = fmaxf(fmaxf(as * acc[j][2], o1.x) + bb.x, 0.0f);
                v1.y = fmaxf(fmaxf(as * acc[j][3], o1.y) + bb.y, 0.0f);
                *reinterpret_cast<float2*>(Cf + (size_t)m0 * DD + c0) = v0;
                *reinterpret_cast<float2*>(Cf + (size_t)(m0 + 8) * DD + c0) = v1;
            }
        }
    }
    #undef CPA
}

// ---------------- host launch ----------------------------------------------------
extern "C" void kernel_launch(void* const* d_in, const int* in_sizes, int n_in,
                              void* d_out, int out_size)
{
    const float* x     = (const float*)d_in[0];
    const float* W     = (const float*)d_in[1];
    const float* alpha = (const float*)d_in[2];
    const float* bias  = (const float*)d_in[3];
    const float* s0    = (const float*)d_in[4];
    const float* s1    = (const float*)d_in[5];
    const float* s2    = (const float*)d_in[6];
    const float* s3    = (const float*)d_in[7];
    float* out = (float*)d_out;

    __nv_bfloat16 *WTh, *WTl, *pTh, *pTl, *t1h, *t1l, *t3h, *t3l;
    float* low;
    cudaGetSymbolAddress((void**)&WTh, g_WT_hi);
    cudaGetSymbolAddress((void**)&WTl, g_WT_lo);
    cudaGetSymbolAddress((void**)&pTh, g_preT_hi);
    cudaGetSymbolAddress((void**)&pTl, g_preT_lo);
    cudaGetSymbolAddress((void**)&t1h, g_t1T_hi);
    cudaGetSymbolAddress((void**)&t1l, g_t1T_lo);
    cudaGetSymbolAddress((void**)&t3h, g_t3T_hi);
    cudaGetSymbolAddress((void**)&t3l, g_t3T_lo);
    cudaGetSymbolAddress((void**)&low, g_low);

    static bool attr_done = false;
    if (!attr_done) {
        cudaFuncSetAttribute(gemm_mma<0>, cudaFuncAttributeMaxDynamicSharedMemorySize, SMEM_TOTAL);
        cudaFuncSetAttribute(gemm_mma<1>, cudaFuncAttributeMaxDynamicSharedMemorySize, SMEM_TOTAL);
        cudaFuncSetAttribute(gemm_mma<2>, cudaFuncAttributeMaxDynamicSharedMemorySize, SMEM_TOTAL);
        cudaFuncSetAttribute(gemm_mma<3>, cudaFuncAttributeMaxDynamicSharedMemorySize, SMEM_TOTAL);
        attr_done = true;
    }

    softmax2_kernel<<<1, 1>>>(alpha);
    wt_split_kernel<<<dim3(16, 16), dim3(32, 32)>>>(W);

    const dim3 grid(DD / CTA_N, NN / CTA_M);   // (4, 32) = 128 CTAs

    // pre^T = (x @ W)^T (split bf16)
    gemm_mma<0><<<grid, 512, SMEM_TOTAL>>>(
        x, nullptr, NN, WTh, WTl, DD,
        nullptr, pTh, pTl, NN, nullptr, nullptr, 0, 0, nullptr, nullptr);
    // merged: t1^T (rows<2048 from s1) + t3^T (rows>=2048 from s3)
    gemm_mma<3><<<grid, 512, SMEM_TOTAL>>>(
        s1, s3, KF, pTh, pTl, NN,
        nullptr, t1h, t1l, KF, t3h, t3l, KH, 0, nullptr, nullptr);
    // low = a0 * (s0 @ t1)
    gemm_mma<1><<<grid, 512, SMEM_TOTAL>>>(
        s0, nullptr, NN, t1h, t1l, KF,
        low, nullptr, nullptr, 0, nullptr, nullptr, 0, 0, nullptr, nullptr);
    // out = relu(max(a1*(s2 @ t3), low) + bias)
    gemm_mma<2><<<grid, 512, SMEM_TOTAL>>>(
        s2, nullptr, NN, t3h, t3l, KH,
        out, nullptr, nullptr, 0, nullptr, nullptr, 1, 1, low, bias);
}